// round 9
// baseline (speedup 1.0000x reference)
#include <cuda_runtime.h>
#include <cuda_bf16.h>
#include <cstdint>

// Problem constants (fixed shapes from reference)
constexpr int B = 256;
constexpr int P = 1024;
constexpr int G = 128;
constexpr float DIST_T2 = 500.0f * 500.0f;   // compare squared distance
constexpr float BBOX_THRESH = 0.1f;
constexpr float SENTINEL = 1.0e15f;          // d2 ~ 3e30: finite, never ties/beats real

constexpr int THREADS = 128;                  // 1 proposal/thread -> max TLP
constexpr int PROPS_PER_CTA = THREADS;        // 128
constexpr int CHUNKS_PB = P / PROPS_PER_CTA;  // 8

__device__ __forceinline__ uint64_t pack2(float lo, float hi) {
    uint64_t r;
    asm("mov.b64 %0, {%1, %2};" : "=l"(r) : "f"(lo), "f"(hi));
    return r;
}

// d2 for a GT pair, entirely inside one asm block so the packed temporaries
// never leak into C++ register allocation (no pack/unpack MOV churn).
// Inputs are pre-negated GT lanes: d = p + (-g).
__device__ __forceinline__ void d2pair(uint64_t X2, uint64_t Y2, uint64_t Z2,
                                       uint64_t gnx, uint64_t gny, uint64_t gnz,
                                       float& a, float& b) {
    asm("{\n\t"
        ".reg .b64 dx, dy, dz, acc;\n\t"
        "add.rn.f32x2 dx, %2, %4;\n\t"
        "add.rn.f32x2 dy, %3, %5;\n\t"
        "add.rn.f32x2 dz, %6, %7;\n\t"
        "mul.rn.f32x2 acc, dz, dz;\n\t"
        "fma.rn.f32x2 acc, dy, dy, acc;\n\t"
        "fma.rn.f32x2 acc, dx, dx, acc;\n\t"
        "mov.b64 {%0, %1}, acc;\n\t"
        "}"
        : "=f"(a), "=f"(b)
        : "l"(X2), "l"(Y2), "l"(gnx), "l"(gny), "l"(Z2), "l"(gnz));
}

__global__ __launch_bounds__(THREADS) void proposal_kernel(
    const float* __restrict__ topk_index,    // [B,P,3]
    const float* __restrict__ topk_confs,    // [B,P]
    const float* __restrict__ bbox_preds,    // [B,P,2]
    const float* __restrict__ gt_3d,         // [B,G,3]
    const float* __restrict__ gt_bbox,       // [B,G,2]
    const int*   __restrict__ num_person,    // [B]
    float*       __restrict__ out)           // [B,P,7]
{
    // Dense pair layout -> 3 x LDS.128 per 2 pairs (4 GT points):
    //   sxy[i] = ( (-gx_{2i},-gx_{2i+1}), (-gy_{2i},-gy_{2i+1}) )   i in [0,64)
    //   szz[k] = ( (-gz_{4k},-gz_{4k+1}), (-gz_{4k+2},-gz_{4k+3}) ) k in [0,32)
    __shared__ ulonglong2 sxy[G / 2];
    __shared__ ulonglong2 szz[G / 4];
    __shared__ float      sb0[G], sb1[G];
    __shared__ float      sout[PROPS_PER_CTA * 7];

    const int tid   = threadIdx.x;
    const int b     = blockIdx.x >> 3;        // 8 chunks per batch
    const int chunk = blockIdx.x & 7;
    const int n     = num_person[b];          // uniform per CTA

    // Stage GT negated (tid == g). Slots g >= n get the sentinel so the
    // padded, remainder-free loop is exact: real slots come first (n >= 1),
    // max real d2 ~ 1.92e8 << sentinel d2 ~ 3e30 (never ties, never wins).
    {
        float ngx = -SENTINEL, ngy = -SENTINEL, ngz = -SENTINEL;
        if (tid < n) {
            const float* g3 = gt_3d + ((size_t)b * G + tid) * 3;
            ngx = -g3[0]; ngy = -g3[1]; ngz = -g3[2];
        }
        float* fxy = reinterpret_cast<float*>(sxy);
        fxy[(tid >> 1) * 4 + (tid & 1)]     = ngx;   // x lane of pair tid>>1
        fxy[(tid >> 1) * 4 + 2 + (tid & 1)] = ngy;   // y lane
        reinterpret_cast<float*>(szz)[tid]  = ngz;   // z lanes, 4 per record
        const float* gb = gt_bbox + ((size_t)b * G + tid) * 2;
        sb0[tid] = gb[0];
        sb1[tid] = gb[1];
    }
    __syncthreads();

    const int    p  = chunk * PROPS_PER_CTA + tid;
    const size_t bp = (size_t)b * P + p;

    const float x = topk_index[bp * 3 + 0];
    const float y = topk_index[bp * 3 + 1];
    const float z = topk_index[bp * 3 + 2];

    // Hoist per-proposal gmem loads so their latency overlaps the loop.
    const float q0 = bbox_preds[bp * 2 + 0];
    const float q1 = bbox_preds[bp * 2 + 1];
    const float cf = topk_confs[bp];

    const uint64_t X2 = pack2(x, x);
    const uint64_t Y2 = pack2(y, y);
    const uint64_t Z2 = pack2(z, z);

    // 4 champions, one per residue class g mod 4 (shorter carried chains).
    // Strict < keeps first-index-within-residue semantics.
    float b0 = 3.402823466e38f, b1 = 3.402823466e38f;
    float b2 = 3.402823466e38f, b3 = 3.402823466e38f;
    int   i0 = 0, i1 = 0, i2 = 0, i3 = 0;

    // n padded to multiple of 8 GT slots -> steps multiple of 2 (unroll-clean)
    const int nsteps = ((n + 7) & ~7) >> 2;   // 4 GT per step
    #pragma unroll 2
    for (int k = 0; k < nsteps; ++k) {
        const ulonglong2 A0 = sxy[2 * k];      // pairs 2k   : LDS.128
        const ulonglong2 A1 = sxy[2 * k + 1];  // pairs 2k+1 : LDS.128
        const ulonglong2 Zk = szz[k];          // both z-pairs: LDS.128

        float d0a, d0b, d1a, d1b;
        d2pair(X2, Y2, Z2, A0.x, A0.y, Zk.x, d0a, d0b);  // g = 4k, 4k+1
        d2pair(X2, Y2, Z2, A1.x, A1.y, Zk.y, d1a, d1b);  // g = 4k+2, 4k+3

        if (d0a < b0) { b0 = d0a; i0 = k; }
        if (d0b < b1) { b1 = d0b; i1 = k; }
        if (d1a < b2) { b2 = d1a; i2 = k; }
        if (d1b < b3) { b3 = d1b; i3 = k; }
    }

    // Exact first-index merge: lexicographic (d2, global index).
    int   g0 = 4 * i0, g1 = 4 * i1 + 1, g2 = 4 * i2 + 2, g3 = 4 * i3 + 3;
    float ba = b0; int ga = g0;
    if ((b1 < ba) || (b1 == ba && g1 < ga)) { ba = b1; ga = g1; }
    if ((b2 < ba) || (b2 == ba && g2 < ga)) { ba = b2; ga = g2; }
    if ((b3 < ba) || (b3 == ba && g3 < ga)) { ba = b3; ga = g3; }

    // dist > 500  <=>  d2 > 500^2 (sqrt monotone; compare-exact)
    const float p2g = (ba > DIST_T2) ? -1.0f : (float)ga;

    const float mb0 = sb0[ga];
    const float mb1 = sb1[ga];
    const bool cond = (p2g >= 0.0f) &&
                      ((q0 < mb0 - BBOX_THRESH) || (q1 < mb1 - BBOX_THRESH));

    // Stage outputs in shared (stride 7 coprime 32 -> conflict-free STS),
    // then copy the contiguous tile to GMEM as float4 (coalesced STG.128).
    float* so = sout + tid * 7;
    so[0] = x;  so[1] = y;  so[2] = z;
    so[3] = p2g; so[4] = cf;
    so[5] = cond ? mb0 : q0;
    so[6] = cond ? mb1 : q1;
    __syncthreads();

    const size_t tile_base = ((size_t)b * P + (size_t)chunk * PROPS_PER_CTA) * 7;
    float4*       dst = reinterpret_cast<float4*>(out + tile_base);
    const float4* src = reinterpret_cast<const float4*>(sout);
    constexpr int NVEC = PROPS_PER_CTA * 7 / 4;   // 224
    #pragma unroll
    for (int i = 0; i < 2; ++i) {
        const int idx = tid + i * THREADS;
        if (idx < NVEC) dst[idx] = src[idx];
    }
}

extern "C" void kernel_launch(void* const* d_in, const int* in_sizes, int n_in,
                              void* d_out, int out_size) {
    const float* topk_index  = (const float*)d_in[0];  // [B,P,3]
    const float* topk_confs  = (const float*)d_in[1];  // [B,P]
    const float* bbox_preds  = (const float*)d_in[2];  // [B,P,2]
    const float* gt_3d       = (const float*)d_in[3];  // [B,G,3]
    const float* gt_bbox     = (const float*)d_in[4];  // [B,G,2]
    const int*   num_person  = (const int*)  d_in[5];  // [B]
    float*       out         = (float*)d_out;          // [B,P,7]

    proposal_kernel<<<B * CHUNKS_PB, THREADS>>>(topk_index, topk_confs, bbox_preds,
                                                gt_3d, gt_bbox, num_person, out);
}